// round 10
// baseline (speedup 1.0000x reference)
#include <cuda_runtime.h>

// GraphNet: 6x GraphConv (norm='both'), N=100000 nodes, E=1600000 edges,
// dims 1->32->64->128->64->32->1, final LeakyReLU(-1) == abs.
//
// Aggregation always happens at min(fi,fo) width: [1,32,64,64,32,1].
// All agg-width buffers fit in L2 (<=25.6MB): gather + red.v4 scatter are
// L2-resident. Dense matmuls are tiny (W in smem).
//
// ns (out_deg^-1/2) is applied EXACTLY ONCE, fused into the scatter gather.
// Pre-matmul kernels (fi>fo layers) must NOT apply it (fixed this round).

#define N_ 100000
#define E_ 1600000

// Scratch (static __device__ globals; allocation is forbidden)
__device__ __align__(16) float g_H[(size_t)N_ * 128];   // node features
__device__ __align__(16) float g_T[(size_t)N_ * 64];    // pre-scatter temp (fi>fo layers)
__device__ __align__(16) float g_A[(size_t)N_ * 64];    // aggregation target
__device__ float g_ns[N_];                              // out_deg^-1/2
__device__ float g_nd[N_];                              // in_deg^-1/2
__device__ int   g_src[E_];
__device__ int   g_dst[E_];
__device__ int   g_is64;                                // 1 if indices are int64

// ---------------------------------------------------------------------------
// Vectorized fire-and-forget float4 reduction (sm_90a+/sm_103a)
__device__ __forceinline__ void red4(float* a, float x, float y, float z, float w) {
    asm volatile("red.global.add.v4.f32 [%0], {%1,%2,%3,%4};"
                 :: "l"(a), "f"(x), "f"(y), "f"(z), "f"(w) : "memory");
}

// ---------------------------------------------------------------------------
__global__ void k_zero_deg() {
    int i = blockIdx.x * blockDim.x + threadIdx.x;
    if (i == 0) g_is64 = 1;
    if (i < N_) { g_ns[i] = 0.f; g_nd[i] = 0.f; }
}

__global__ void k_zero_A(int n) {
    int i = blockIdx.x * blockDim.x + threadIdx.x;
    if (i < n) g_A[i] = 0.f;
}

// Detect index dtype. View src as int32 words; only touch the first E_ words,
// in-bounds for either dtype. int64 (LE, values < 2^31): all odd words are 0.
// int32: odd words are real indices -> some nonzero among 800K samples.
__global__ void k_detect(const int* __restrict__ s32) {
    int i = blockIdx.x * blockDim.x + threadIdx.x;
    int idx = 2 * i + 1;
    if (idx < E_ && s32[idx] != 0) g_is64 = 0;
}

// Convert indices to int32 and count degrees in one pass.
__global__ void k_idx_deg(const int* __restrict__ s32,
                          const int* __restrict__ d32) {
    int e = blockIdx.x * blockDim.x + threadIdx.x;
    if (e >= E_) return;
    int pos = g_is64 ? 2 * e : e;   // low word of int64, or the int32 itself
    int s = s32[pos];
    int d = d32[pos];
    g_src[e] = s;
    g_dst[e] = d;
    atomicAdd(&g_ns[s], 1.0f);   // out-degree
    atomicAdd(&g_nd[d], 1.0f);   // in-degree
}

__global__ void k_norm() {
    int i = blockIdx.x * blockDim.x + threadIdx.x;
    if (i < N_) {
        g_ns[i] = rsqrtf(fmaxf(g_ns[i], 1.0f));
        g_nd[i] = rsqrtf(fmaxf(g_nd[i], 1.0f));
    }
}

// ---------------------------------------------------------------------------
// Scalar scatter (C=1). feat = external x (use_ext=1) or g_T (use_ext=0).
// ns fused here (the ONLY place it is applied).
__global__ void k_scatter1(const float* __restrict__ ext, int use_ext) {
    int e = blockIdx.x * blockDim.x + threadIdx.x;
    if (e >= E_) return;
    const float* f = use_ext ? ext : g_T;
    int s = g_src[e];
    atomicAdd(&g_A[g_dst[e]], f[s] * g_ns[s]);
}

// Vector scatter: C channels, one float4-group per thread.
// feat = g_T (use_T=1) or g_H (use_T=0). ns fused here (the ONLY place).
template <int C>
__global__ void k_scatterv(int use_T) {
    constexpr int G = C / 4;
    int tid = blockIdx.x * blockDim.x + threadIdx.x;
    if (tid >= E_ * G) return;
    int e = tid / G;            // power-of-two: compiles to shift
    int g = tid % G;
    const float* __restrict__ f = use_T ? g_T : g_H;
    int s = g_src[e];
    int d = g_dst[e];
    float ns = g_ns[s];
    float4 v = *(const float4*)(f + (size_t)s * C + g * 4);
    red4(g_A + (size_t)d * C + g * 4, v.x * ns, v.y * ns, v.z * ns, v.w * ns);
}

// ---------------------------------------------------------------------------
// Layer 0 epilogue: H[i,o] = A[i] * nd[i] * W0[o] + b0[o]  (fo=32)
__global__ void k_expand(const float* __restrict__ W, const float* __restrict__ b) {
    int t = blockIdx.x * blockDim.x + threadIdx.x;
    if (t >= N_ * 32) return;
    int i = t >> 5, o = t & 31;
    g_H[t] = g_A[i] * g_nd[i] * W[o] + b[o];
}

// Post-aggregation matmul (fi<=fo layers): H = nd * (A @ W) + b
template <int FI, int FO, int NB>
__global__ void k_mm_post(const float* __restrict__ W, const float* __restrict__ b) {
    __shared__ float Ws[FI * FO];
    int tx = threadIdx.x, ty = threadIdx.y;
    int tid = ty * FO + tx;
    for (int i = tid; i < FI * FO; i += FO * NB) Ws[i] = W[i];
    __syncthreads();
    int node = blockIdx.x * NB + ty;
    if (node >= N_) return;
    float nd = g_nd[node];
    const float* __restrict__ row = g_A + (size_t)node * FI;
    float s = 0.f;
#pragma unroll
    for (int c = 0; c < FI; c++) s += row[c] * Ws[c * FO + tx];
    g_H[(size_t)node * FO + tx] = s * nd + b[tx];
}

// Pre-aggregation matmul (fi>fo layers): T = H @ W   (NO ns here; scatter does it)
template <int FI, int FO, int NB>
__global__ void k_mm_pre(const float* __restrict__ W) {
    __shared__ float Ws[FI * FO];
    int tx = threadIdx.x, ty = threadIdx.y;
    int tid = ty * FO + tx;
    for (int i = tid; i < FI * FO; i += FO * NB) Ws[i] = W[i];
    __syncthreads();
    int node = blockIdx.x * NB + ty;
    if (node >= N_) return;
    const float* __restrict__ row = g_H + (size_t)node * FI;
    float s = 0.f;
#pragma unroll
    for (int c = 0; c < FI; c++) s += row[c] * Ws[c * FO + tx];
    g_T[(size_t)node * FO + tx] = s;
}

// fi>fo epilogue: H[i,c] = A[i,c] * nd[i] + b[c]
template <int C>
__global__ void k_scale_bias(const float* __restrict__ b) {
    int t = blockIdx.x * blockDim.x + threadIdx.x;
    if (t >= N_ * C) return;
    int i = t / C, c = t % C;
    g_H[t] = g_A[t] * g_nd[i] + b[c];
}

// Layer 5 pre: T[i] = dot(H[i,:32], W5)   (NO ns here; scatter does it)
__global__ void k_mv_pre(const float* __restrict__ W) {
    int i = blockIdx.x * blockDim.x + threadIdx.x;
    if (i >= N_) return;
    const float4* __restrict__ row = (const float4*)(g_H + (size_t)i * 32);
    float s = 0.f;
#pragma unroll
    for (int q = 0; q < 8; q++) {
        float4 v = row[q];
        s += v.x * W[4 * q] + v.y * W[4 * q + 1] + v.z * W[4 * q + 2] + v.w * W[4 * q + 3];
    }
    g_T[i] = s;
}

// Layer 5 epilogue: out[i] = | A[i]*nd[i] + b5 |
__global__ void k_final(const float* __restrict__ b, float* __restrict__ out) {
    int i = blockIdx.x * blockDim.x + threadIdx.x;
    if (i >= N_) return;
    float v = g_A[i] * g_nd[i] + b[0];
    out[i] = fabsf(v);
}

// ---------------------------------------------------------------------------
extern "C" void kernel_launch(void* const* d_in, const int* in_sizes, int n_in,
                              void* d_out, int out_size) {
    const float* x   = (const float*)d_in[0];
    const int*   src = (const int*)d_in[1];   // int32 view; dtype detected on-device
    const int*   dst = (const int*)d_in[2];
    const float *W0 = (const float*)d_in[3],  *b0 = (const float*)d_in[4];
    const float *W1 = (const float*)d_in[5],  *b1 = (const float*)d_in[6];
    const float *W2 = (const float*)d_in[7],  *b2 = (const float*)d_in[8];
    const float *W3 = (const float*)d_in[9],  *b3 = (const float*)d_in[10];
    const float *W4 = (const float*)d_in[11], *b4 = (const float*)d_in[12];
    const float *W5 = (const float*)d_in[13], *b5 = (const float*)d_in[14];
    float* out = (float*)d_out;

    const int T = 256;
    auto nb = [](long long n, int t) { return (int)((n + t - 1) / t); };

    // Index dtype detection + degrees + norms
    k_zero_deg<<<nb(N_, T), T>>>();
    k_detect<<<nb(E_ / 2, T), T>>>(src);
    k_idx_deg<<<nb(E_, T), T>>>(src, dst);
    k_norm<<<nb(N_, T), T>>>();

    // Layer 0: 1 -> 32 (agg C=1, W after)
    k_zero_A<<<nb(N_, T), T>>>(N_);
    k_scatter1<<<nb(E_, T), T>>>(x, 1);
    k_expand<<<nb((long long)N_ * 32, T), T>>>(W0, b0);

    // Layer 1: 32 -> 64 (agg C=32, W after)
    k_zero_A<<<nb((long long)N_ * 32, T), T>>>(N_ * 32);
    k_scatterv<32><<<nb((long long)E_ * 8, T), T>>>(0);
    k_mm_post<32, 64, 8><<<nb(N_, 8), dim3(64, 8)>>>(W1, b1);

    // Layer 2: 64 -> 128 (agg C=64, W after)
    k_zero_A<<<nb((long long)N_ * 64, T), T>>>(N_ * 64);
    k_scatterv<64><<<nb((long long)E_ * 16, T), T>>>(0);
    k_mm_post<64, 128, 4><<<nb(N_, 4), dim3(128, 4)>>>(W2, b2);

    // Layer 3: 128 -> 64 (W before, agg C=64)
    k_mm_pre<128, 64, 8><<<nb(N_, 8), dim3(64, 8)>>>(W3);
    k_zero_A<<<nb((long long)N_ * 64, T), T>>>(N_ * 64);
    k_scatterv<64><<<nb((long long)E_ * 16, T), T>>>(1);
    k_scale_bias<64><<<nb((long long)N_ * 64, T), T>>>(b3);

    // Layer 4: 64 -> 32 (W before, agg C=32)
    k_mm_pre<64, 32, 16><<<nb(N_, 16), dim3(32, 16)>>>(W4);
    k_zero_A<<<nb((long long)N_ * 32, T), T>>>(N_ * 32);
    k_scatterv<32><<<nb((long long)E_ * 8, T), T>>>(1);
    k_scale_bias<32><<<nb((long long)N_ * 32, T), T>>>(b4);

    // Layer 5: 32 -> 1 (W before, agg C=1)
    k_mv_pre<<<nb(N_, T), T>>>(W5);
    k_zero_A<<<nb(N_, T), T>>>(N_);
    k_scatter1<<<nb(E_, T), T>>>(nullptr, 0);
    k_final<<<nb(N_, T), T>>>(b5, out);
}

// round 12
// speedup vs baseline: 7.1623x; 7.1623x over previous
#include <cuda_runtime.h>

// GraphNet: 6x GraphConv (norm='both'), N=100000, E=1600000,
// dims 1->32->64->128->64->32->1, final abs.
//
// No inter-layer nonlinearity => the net is linear in x. Since S (scatter),
// ns*, nd* act on the node dim and the W's on the channel dim, every layer is
// h' = (nd . S(ns . h)) @ W + b. Expanding all 6 layers:
//   out = | nd.(A6*sa + B5*s0 + B4*s1 + B3*s2 + B2*s3 + B1*s4) + b5 |
// with scalar chains A1=S(ns.x), A_{k+1}=S(nsnd.A_k); B1=S(ns),
// B_{k+1}=S(nsnd.B_k); and sigma = chained weight products (k_alg).
// Wide features are never materialized: 6 scalar/float2 edge passes total.
//
// IMPORTANT: all __device__ globals are referenced ONLY from device code
// (passing them as kernel args from host passes the host shadow address -> UB;
// that was the R11 bug).

#define N_ 100000
#define E_ 1600000

// ---- device scratch (no allocation allowed) ----
__device__ int2  g_edge[E_];
__device__ float g_ns[N_], g_nd[N_], g_nsnd[N_];
__device__ __align__(8) float2 g_c1[N_];   // {ns*x, ns}
__device__ __align__(8) float2 g_P1[N_];   // {A1, B1}
__device__ __align__(8) float2 g_P2[N_];   // {A2, B2}
__device__ __align__(8) float2 g_P3[N_];   // {A3, B3}
__device__ __align__(8) float2 g_P4[N_];   // {A4, B4}
__device__ float g_u4[N_];                 // A5
__device__ float g_zc[N_];                 // pre-final per-node coefficient
__device__ float g_y[N_];                  // A6-combined (post S)
__device__ float g_sig[8];                 // sa, s0..s4
__device__ int   g_is64;

// Vectorized fire-and-forget float2 reduction (sm_90+)
__device__ __forceinline__ void red2(float2* a, float x, float y) {
    asm volatile("red.global.add.v2.f32 [%0], {%1,%2};"
                 :: "l"(a), "f"(x), "f"(y) : "memory");
}

// ---------------------------------------------------------------------------
__global__ void k_init() {
    int i = blockIdx.x * blockDim.x + threadIdx.x;
    if (i == 0) g_is64 = 1;
    if (i < N_) {
        g_ns[i] = 0.f; g_nd[i] = 0.f;
        float2 z = make_float2(0.f, 0.f);
        g_P1[i] = z; g_P2[i] = z; g_P3[i] = z; g_P4[i] = z;
        g_u4[i] = 0.f; g_y[i] = 0.f;
    }
}

// Detect index dtype: view src as int32 words over first E_ words (in-bounds
// either way). int64 LE (values < 2^31): odd words all 0. int32: some odd
// word nonzero among 800K samples.
__global__ void k_detect(const int* __restrict__ s32) {
    int i = blockIdx.x * blockDim.x + threadIdx.x;
    int idx = 2 * i + 1;
    if (idx < E_ && s32[idx] != 0) g_is64 = 0;
}

// Convert indices, pack edges, count degrees.
__global__ void k_idx_deg(const int* __restrict__ s32,
                          const int* __restrict__ d32) {
    int e = blockIdx.x * blockDim.x + threadIdx.x;
    if (e >= E_) return;
    int pos = g_is64 ? 2 * e : e;
    int s = s32[pos];
    int d = d32[pos];
    g_edge[e] = make_int2(s, d);
    atomicAdd(&g_ns[s], 1.0f);   // out-degree
    atomicAdd(&g_nd[d], 1.0f);   // in-degree
}

// Norms + fused first-pass coefficient pair {ns*x, ns}.
__global__ void k_norm(const float* __restrict__ x) {
    int i = blockIdx.x * blockDim.x + threadIdx.x;
    if (i >= N_) return;
    float ns = rsqrtf(fmaxf(g_ns[i], 1.0f));
    float nd = rsqrtf(fmaxf(g_nd[i], 1.0f));
    g_ns[i] = ns; g_nd[i] = nd; g_nsnd[i] = ns * nd;
    g_c1[i] = make_float2(ns * x[i], ns);
}

// Edge scatter passes. All buffers referenced directly (device symbols).
template <int STAGE>
__global__ void k_pass() {
    int e = blockIdx.x * blockDim.x + threadIdx.x;
    if (e >= E_) return;
    int2 ed = g_edge[e];
    if constexpr (STAGE == 1) {
        float2 p = g_c1[ed.x];
        red2(g_P1 + ed.y, p.x, p.y);
    } else if constexpr (STAGE == 2) {
        float2 p = g_P1[ed.x]; float m = g_nsnd[ed.x];
        red2(g_P2 + ed.y, p.x * m, p.y * m);
    } else if constexpr (STAGE == 3) {
        float2 p = g_P2[ed.x]; float m = g_nsnd[ed.x];
        red2(g_P3 + ed.y, p.x * m, p.y * m);
    } else if constexpr (STAGE == 4) {
        float2 p = g_P3[ed.x]; float m = g_nsnd[ed.x];
        red2(g_P4 + ed.y, p.x * m, p.y * m);
    } else if constexpr (STAGE == 5) {
        atomicAdd(&g_u4[ed.y], g_nsnd[ed.x] * g_P4[ed.x].x);   // A5
    } else {  // STAGE == 6
        atomicAdd(&g_y[ed.y], g_zc[ed.x]);
    }
}

// ---------------------------------------------------------------------------
// Dense algebra -> 6 scalars.
// p1=W0@W1, q1=b0@W1; {p1,q1,b1}@W2; @W3 (+b2@W3); @W4 (+b3@W4);
// @W5 -> sa=W0..W5, s0=b0W1..W5, s1=b1W2..W5, s2=b2W3W4W5, s3=b3W4W5, s4=b4@W5.
__global__ void k_alg(const float* __restrict__ W0, const float* __restrict__ b0,
                      const float* __restrict__ W1, const float* __restrict__ b1,
                      const float* __restrict__ W2, const float* __restrict__ b2,
                      const float* __restrict__ W3, const float* __restrict__ b3,
                      const float* __restrict__ W4, const float* __restrict__ b4,
                      const float* __restrict__ W5) {
    __shared__ float p1[64], q1[64];
    __shared__ float tP[128], tQ[128], tR[128];
    __shared__ float p2[64], q2[64], r2[64], s2[64];
    __shared__ float p3[32], q3[32], r3[32], s3[32], t3[32];
    int t = threadIdx.x;  // 128 threads

    if (t < 64) {
        float a = 0.f, b = 0.f;
        for (int c = 0; c < 32; c++) { a += W0[c] * W1[c * 64 + t]; b += b0[c] * W1[c * 64 + t]; }
        p1[t] = a; q1[t] = b;
    }
    __syncthreads();
    {
        float a = 0.f, b = 0.f, r = 0.f;
        for (int c = 0; c < 64; c++) {
            float w = W2[c * 128 + t];
            a += p1[c] * w; b += q1[c] * w; r += b1[c] * w;
        }
        tP[t] = a; tQ[t] = b; tR[t] = r;
    }
    __syncthreads();
    if (t < 64) {
        float a = 0.f, b = 0.f, r = 0.f, s = 0.f;
        for (int k = 0; k < 128; k++) {
            float w = W3[k * 64 + t];
            a += tP[k] * w; b += tQ[k] * w; r += tR[k] * w; s += b2[k] * w;
        }
        p2[t] = a; q2[t] = b; r2[t] = r; s2[t] = s;
    }
    __syncthreads();
    if (t < 32) {
        float a = 0.f, b = 0.f, r = 0.f, s = 0.f, tt = 0.f;
        for (int c = 0; c < 64; c++) {
            float w = W4[c * 32 + t];
            a += p2[c] * w; b += q2[c] * w; r += r2[c] * w; s += s2[c] * w; tt += b3[c] * w;
        }
        p3[t] = a; q3[t] = b; r3[t] = r; s3[t] = s; t3[t] = tt;
    }
    __syncthreads();
    if (t == 0) {
        float sa = 0.f, s0 = 0.f, s1 = 0.f, ss2 = 0.f, ss3 = 0.f, s4 = 0.f;
        for (int c = 0; c < 32; c++) {
            float w = W5[c];
            sa += p3[c] * w; s0 += q3[c] * w; s1 += r3[c] * w;
            ss2 += s3[c] * w; ss3 += t3[c] * w; s4 += b4[c] * w;
        }
        g_sig[0] = sa; g_sig[1] = s0; g_sig[2] = s1;
        g_sig[3] = ss2; g_sig[4] = ss3; g_sig[5] = s4;
    }
}

// zc = ns * ( nd*(A5*sa + B4*s0 + B3*s1 + B2*s2 + B1*s3) + s4 )
__global__ void k_zc() {
    int i = blockIdx.x * blockDim.x + threadIdx.x;
    if (i >= N_) return;
    float z = g_nd[i] * (g_u4[i]   * g_sig[0] +
                         g_P4[i].y * g_sig[1] +
                         g_P3[i].y * g_sig[2] +
                         g_P2[i].y * g_sig[3] +
                         g_P1[i].y * g_sig[4]) + g_sig[5];
    g_zc[i] = g_ns[i] * z;
}

// out = | nd*y + b5 |
__global__ void k_final(const float* __restrict__ b5, float* __restrict__ out) {
    int i = blockIdx.x * blockDim.x + threadIdx.x;
    if (i >= N_) return;
    out[i] = fabsf(g_nd[i] * g_y[i] + b5[0]);
}

// ---------------------------------------------------------------------------
extern "C" void kernel_launch(void* const* d_in, const int* in_sizes, int n_in,
                              void* d_out, int out_size) {
    const float* x   = (const float*)d_in[0];
    const int*   src = (const int*)d_in[1];   // int32 view; dtype detected on-device
    const int*   dst = (const int*)d_in[2];
    const float *W0 = (const float*)d_in[3],  *b0 = (const float*)d_in[4];
    const float *W1 = (const float*)d_in[5],  *b1 = (const float*)d_in[6];
    const float *W2 = (const float*)d_in[7],  *b2 = (const float*)d_in[8];
    const float *W3 = (const float*)d_in[9],  *b3 = (const float*)d_in[10];
    const float *W4 = (const float*)d_in[11], *b4 = (const float*)d_in[12];
    const float *W5 = (const float*)d_in[13], *b5 = (const float*)d_in[14];
    float* out = (float*)d_out;

    const int T = 256;
    auto nb = [](long long n, int t) { return (int)((n + t - 1) / t); };
    int gN = nb(N_, T), gE = nb(E_, T);

    k_init<<<gN, T>>>();
    k_detect<<<nb(E_ / 2, T), T>>>(src);
    k_idx_deg<<<gE, T>>>(src, dst);
    k_norm<<<gN, T>>>(x);
    k_alg<<<1, 128>>>(W0, b0, W1, b1, W2, b2, W3, b3, W4, b4, W5);

    k_pass<1><<<gE, T>>>();   // {A1, B1}
    k_pass<2><<<gE, T>>>();   // {A2, B2}
    k_pass<3><<<gE, T>>>();   // {A3, B3}
    k_pass<4><<<gE, T>>>();   // {A4, B4}
    k_pass<5><<<gE, T>>>();   // A5

    k_zc<<<gN, T>>>();
    k_pass<6><<<gE, T>>>();   // y = S(zc)
    k_final<<<gN, T>>>(b5, out);
}

// round 14
// speedup vs baseline: 7.7690x; 1.0847x over previous
#include <cuda_runtime.h>

// GraphNet: 6x GraphConv (norm='both'), N=100000, E=1600000,
// dims 1->32->64->128->64->32->1, final abs.
//
// Linear net => rank-collapse to scalar chains. Single-chain formulation:
//   A1 = S(ns.x), B1 = S(ns)                        (pass1, float2)
//   Z2 = S(nsnd . sa.A1)                            (pass2)
//   Z_{k+1} = S(nsnd . (Z_k + c_k.B1)), c=(s0,s1,s2,s3) at stages 3..6
//   out = | nd.(Z6 + s4.B1) + b5 |
// Matches y = sa.A6 + s0.B5 + s1.B4 + s2.B3 + s3.B2 + s4.B1 (each injected
// c.B1 ages one generation per remaining scatter; stage-2 injection is 0).
// Prep kernels (N-sized) build G = nsnd.(Z + c.B1) and zero the next target,
// so edge passes are 16B/edge: edge(8) + G[s](4, L2-resident) + RED.32(4).
//
// All __device__ globals referenced ONLY from device code (host shadow-symbol
// pitfall). sigma scalars come from k_alg (tiny dense chain of W products).

#define N_ 100000
#define E_ 1600000

__device__ int2  g_edge[E_];
__device__ float g_ns[N_], g_nd[N_], g_nsnd[N_];
__device__ __align__(8) float2 g_c1[N_];   // {ns*x, ns}
__device__ __align__(8) float2 g_P1[N_];   // {A1, B1}
__device__ float g_Z[5][N_];               // Z2..Z6
__device__ float g_G[N_];                  // prep output (gather source)
__device__ float g_sig[8];                 // sa, s0, s1, s2, s3, s4
__device__ int   g_is64;

// ---------------------------------------------------------------------------
__device__ __forceinline__ void red2(float2* a, float x, float y) {
    asm volatile("red.global.add.v2.f32 [%0], {%1,%2};"
                 :: "l"(a), "f"(x), "f"(y) : "memory");
}
__device__ __forceinline__ void red1(float* a, float x) {
    asm volatile("red.global.add.f32 [%0], %1;" :: "l"(a), "f"(x) : "memory");
}

// ---------------------------------------------------------------------------
__global__ void k_init() {
    int i = blockIdx.x * blockDim.x + threadIdx.x;
    if (i == 0) g_is64 = 1;
    if (i < N_) {
        g_ns[i] = 0.f; g_nd[i] = 0.f;
        g_P1[i] = make_float2(0.f, 0.f);
    }
}

// Index dtype detection: int32 view over first E_ words (in-bounds either way).
// int64 LE (< 2^31): odd words all zero. int32: some odd word nonzero.
__global__ void k_detect(const int* __restrict__ s32) {
    int i = blockIdx.x * blockDim.x + threadIdx.x;
    int idx = 2 * i + 1;
    if (idx < E_ && s32[idx] != 0) g_is64 = 0;
}

__global__ void k_idx_deg(const int* __restrict__ s32,
                          const int* __restrict__ d32) {
    int e = blockIdx.x * blockDim.x + threadIdx.x;
    if (e >= E_) return;
    int pos = g_is64 ? 2 * e : e;
    int s = s32[pos];
    int d = d32[pos];
    g_edge[e] = make_int2(s, d);
    red1(&g_ns[s], 1.0f);   // out-degree
    red1(&g_nd[d], 1.0f);   // in-degree
}

__global__ void k_norm(const float* __restrict__ x) {
    int i = blockIdx.x * blockDim.x + threadIdx.x;
    if (i >= N_) return;
    float ns = rsqrtf(fmaxf(g_ns[i], 1.0f));
    float nd = rsqrtf(fmaxf(g_nd[i], 1.0f));
    g_ns[i] = ns; g_nd[i] = nd; g_nsnd[i] = ns * nd;
    g_c1[i] = make_float2(ns * x[i], ns);
}

// Pass 1: {A1, B1} = S({ns*x, ns})
__global__ void k_pass1() {
    int e = blockIdx.x * blockDim.x + threadIdx.x;
    if (e >= E_) return;
    int2 ed = g_edge[e];
    float2 p = g_c1[ed.x];
    red2(g_P1 + ed.y, p.x, p.y);
}

// Prep stage k (2..6): G = nsnd * (src + c * B1); zero next scatter target.
// stage 2: src = sa*A1, c = 0. stage k>=3: src = Z_{k-1}, c = sig[k-2].
template <int STAGE>
__global__ void k_prep() {
    int i = blockIdx.x * blockDim.x + threadIdx.x;
    if (i >= N_) return;
    float v;
    if constexpr (STAGE == 2) {
        v = g_sig[0] * g_P1[i].x;
    } else {
        v = g_Z[STAGE - 3][i] + g_sig[STAGE - 2] * g_P1[i].y;
    }
    g_G[i] = g_nsnd[i] * v;
    g_Z[STAGE - 2][i] = 0.f;
}

// Scalar edge pass into Z_{STAGE}
template <int STAGE>
__global__ void k_pass() {
    int e = blockIdx.x * blockDim.x + threadIdx.x;
    if (e >= E_) return;
    int2 ed = g_edge[e];
    red1(&g_Z[STAGE - 2][ed.y], g_G[ed.x]);
}

// ---------------------------------------------------------------------------
// Dense algebra -> sigma: sa=W0..W5, s0=b0W1..W5, s1=b1W2..W5, s2=b2W3W4W5,
// s3=b3W4W5, s4=b4W5.
__global__ void k_alg(const float* __restrict__ W0, const float* __restrict__ b0,
                      const float* __restrict__ W1, const float* __restrict__ b1,
                      const float* __restrict__ W2, const float* __restrict__ b2,
                      const float* __restrict__ W3, const float* __restrict__ b3,
                      const float* __restrict__ W4, const float* __restrict__ b4,
                      const float* __restrict__ W5) {
    __shared__ float p1[64], q1[64];
    __shared__ float tP[128], tQ[128], tR[128];
    __shared__ float p2[64], q2[64], r2[64], s2[64];
    __shared__ float p3[32], q3[32], r3[32], s3[32], t3[32];
    int t = threadIdx.x;  // 128 threads

    if (t < 64) {
        float a = 0.f, b = 0.f;
        for (int c = 0; c < 32; c++) { a += W0[c] * W1[c * 64 + t]; b += b0[c] * W1[c * 64 + t]; }
        p1[t] = a; q1[t] = b;
    }
    __syncthreads();
    {
        float a = 0.f, b = 0.f, r = 0.f;
        for (int c = 0; c < 64; c++) {
            float w = W2[c * 128 + t];
            a += p1[c] * w; b += q1[c] * w; r += b1[c] * w;
        }
        tP[t] = a; tQ[t] = b; tR[t] = r;
    }
    __syncthreads();
    if (t < 64) {
        float a = 0.f, b = 0.f, r = 0.f, s = 0.f;
        for (int k = 0; k < 128; k++) {
            float w = W3[k * 64 + t];
            a += tP[k] * w; b += tQ[k] * w; r += tR[k] * w; s += b2[k] * w;
        }
        p2[t] = a; q2[t] = b; r2[t] = r; s2[t] = s;
    }
    __syncthreads();
    if (t < 32) {
        float a = 0.f, b = 0.f, r = 0.f, s = 0.f, tt = 0.f;
        for (int c = 0; c < 64; c++) {
            float w = W4[c * 32 + t];
            a += p2[c] * w; b += q2[c] * w; r += r2[c] * w; s += s2[c] * w; tt += b3[c] * w;
        }
        p3[t] = a; q3[t] = b; r3[t] = r; s3[t] = s; t3[t] = tt;
    }
    __syncthreads();
    if (t == 0) {
        float sa = 0.f, s0 = 0.f, s1 = 0.f, ss2 = 0.f, ss3 = 0.f, s4 = 0.f;
        for (int c = 0; c < 32; c++) {
            float w = W5[c];
            sa += p3[c] * w; s0 += q3[c] * w; s1 += r3[c] * w;
            ss2 += s3[c] * w; ss3 += t3[c] * w; s4 += b4[c] * w;
        }
        g_sig[0] = sa; g_sig[1] = s0; g_sig[2] = s1;
        g_sig[3] = ss2; g_sig[4] = ss3; g_sig[5] = s4;
    }
}

// out = | nd * (Z6 + s4*B1) + b5 |
__global__ void k_final(const float* __restrict__ b5, float* __restrict__ out) {
    int i = blockIdx.x * blockDim.x + threadIdx.x;
    if (i >= N_) return;
    float y = g_Z[4][i] + g_sig[5] * g_P1[i].y;
    out[i] = fabsf(g_nd[i] * y + b5[0]);
}

// ---------------------------------------------------------------------------
extern "C" void kernel_launch(void* const* d_in, const int* in_sizes, int n_in,
                              void* d_out, int out_size) {
    const float* x   = (const float*)d_in[0];
    const int*   src = (const int*)d_in[1];   // int32 view; dtype detected on-device
    const int*   dst = (const int*)d_in[2];
    const float *W0 = (const float*)d_in[3],  *b0 = (const float*)d_in[4];
    const float *W1 = (const float*)d_in[5],  *b1 = (const float*)d_in[6];
    const float *W2 = (const float*)d_in[7],  *b2 = (const float*)d_in[8];
    const float *W3 = (const float*)d_in[9],  *b3 = (const float*)d_in[10];
    const float *W4 = (const float*)d_in[11], *b4 = (const float*)d_in[12];
    const float *W5 = (const float*)d_in[13], *b5 = (const float*)d_in[14];
    float* out = (float*)d_out;

    const int T = 256;
    auto nb = [](long long n, int t) { return (int)((n + t - 1) / t); };
    int gN = nb(N_, T), gE = nb(E_, T);

    k_init<<<gN, T>>>();
    k_detect<<<nb(E_ / 2, T), T>>>(src);
    k_idx_deg<<<gE, T>>>(src, dst);
    k_norm<<<gN, T>>>(x);
    k_alg<<<1, 128>>>(W0, b0, W1, b1, W2, b2, W3, b3, W4, b4, W5);

    k_pass1<<<gE, T>>>();                 // {A1, B1}

    k_prep<2><<<gN, T>>>();  k_pass<2><<<gE, T>>>();   // Z2
    k_prep<3><<<gN, T>>>();  k_pass<3><<<gE, T>>>();   // Z3
    k_prep<4><<<gN, T>>>();  k_pass<4><<<gE, T>>>();   // Z4
    k_prep<5><<<gN, T>>>();  k_pass<5><<<gE, T>>>();   // Z5
    k_prep<6><<<gN, T>>>();  k_pass<6><<<gE, T>>>();   // Z6

    k_final<<<gN, T>>>(b5, out);
}